// round 17
// baseline (speedup 1.0000x reference)
#include <cuda_runtime.h>

// LSTM_53815940218945: B=8192, T=256, I=1, H=50, O=1, fp32.
//
// R16 = R12's ME=4 register tile (FMA-bound: 24 LDS-wf per 64 fma-cyc per
// warp-k4) + R15's warp-parallel structure (named-barrier subgroups, fused
// epilogue, smem bias tables). R15 proved 28 warps kills the latency wall
// but its ME=2 tile was LSU-bound (L1=71.6%); R12 proved ME=4 is FMA-bound
// (L1=43%) but had too few warps (issue=46%). This takes both.
//
//   CTA = 448 thr = 2 subgroups x 224 (7 warps; 208 active = 8e x 26u,
//   16 pad threads compute clones, stores suppressed). ME=4 -> 32 el per
//   subgroup, 64 per CTA, grid=128, 14 warps/SM, 1 barrier(224)/step.
//
// Geometry: warp = 8 eIdx x 4 uIdx. W rows [4*52][52]: u-stride 104 fl
// = bank+8 -> 4 unique addrs, conflict-free. h stride 60 -> eIdx banks
// {0,28,24,20,16,12,8,4} distinct. All v2 accesses 8B/16B aligned.

#define T_LEN 256
#define HID   50
#define KD    52            // k width (padded)
#define RPAD  52            // rows per gate (UT*NU)
#define HSTR  60            // h row stride (bank-clean for ET=8)
#define ET    8
#define ME    4
#define EPS   32            // elements per subgroup
#define NU    2
#define ACT_T 208           // active threads per subgroup (8e x 26u)
#define SUBT  224           // padded to 7 warps (bar.sync-legal)
#define SUBS  2
#define NTHR  448
#define EPB   64            // elements per CTA
#define NROW  8

// smem layout (float offsets)
#define F_W    0
#define FW_SZ  (4*RPAD*KD)           // 10816
#define F_H    FW_SZ
#define FH_SUB (2*EPS*HSTR)          // 3840 per subgroup (2 buffers)
#define FH_SZ  (SUBS*FH_SUB)         // 7680
#define F_BIAS (F_H + FH_SZ)         // 18496
#define F_WIH  (F_BIAS + 4*RPAD)
#define F_WL   (F_WIH + 4*RPAD)
#define F_BL   (F_WL + 52)
#define SM_TOT ((F_BL + 4) * 4)      // ~76.3 KB dynamic smem

__device__ __forceinline__ float fast_ex2(float x) {
    float y; asm("ex2.approx.f32 %0, %1;" : "=f"(y) : "f"(x)); return y;
}
__device__ __forceinline__ float fast_rcp(float x) {
    float y; asm("rcp.approx.f32 %0, %1;" : "=f"(y) : "f"(x)); return y;
}
__device__ __forceinline__ void ffma2(unsigned long long& d,
                                      unsigned long long a,
                                      unsigned long long b) {
    asm("fma.rn.f32x2 %0, %1, %2, %0;" : "+l"(d) : "l"(a), "l"(b));
}
union U64F2 { unsigned long long u; float2 f; };

__global__ __launch_bounds__(NTHR, 1)
void lstm_r16_kernel(const float* __restrict__ x,
                     const float* __restrict__ W_ih,
                     const float* __restrict__ W_hh,
                     const float* __restrict__ b_ih,
                     const float* __restrict__ b_hh,
                     const float* __restrict__ W_lin,
                     const float* __restrict__ b_lin,
                     float* __restrict__ out, int B)
{
    extern __shared__ __align__(16) float sm[];
    float* sW    = sm + F_W;      // [4*RPAD][KD], zero-padded
    float* sH    = sm + F_H;      // SUBS x 2 x [EPS][HSTR]
    float* sBias = sm + F_BIAS;   // [4*RPAD]
    float* sWih  = sm + F_WIH;    // [4*RPAD]
    float* sWl   = sm + F_WL;
    float* sBl   = sm + F_BL;

    const int tid = threadIdx.x;

    // ---- cooperative staging ----
    for (int i = tid; i < FW_SZ; i += NTHR) {
        const int row = i / KD, k = i - row * KD;
        const int gate = row / RPAD, u = row - gate * RPAD;
        sW[i] = (u < HID && k < HID) ? W_hh[(gate * HID + u) * HID + k] : 0.0f;
    }
    for (int i = tid; i < FH_SZ; i += NTHR) sH[i] = 0.0f;
    for (int i = tid; i < 4 * RPAD; i += NTHR) {
        const int gate = i / RPAD, u = i - gate * RPAD;
        const bool v = (u < HID);
        const int row = gate * HID + u;
        sBias[i] = v ? (b_ih[row] + b_hh[row]) : 0.0f;
        sWih[i]  = v ? W_ih[row] : 0.0f;        // I=1
    }
    if (tid < 52) sWl[tid] = (tid < HID) ? W_lin[tid] : 0.0f;
    if (tid == 0) sBl[0] = b_lin[0];
    __syncthreads();

    const int sub    = tid / SUBT;         // 0..1
    const int st     = tid - sub * SUBT;   // 0..223
    const bool live  = (st < ACT_T);       // pad threads clone (e0,u0), no stores
    const int eIdx   = live ? (st & (ET - 1)) : 0;
    const int u0     = live ? ((st >> 3) * NU) : 0;   // 0..50 even

    // x pointers for my ME=4 elements (el = base + m*8); clamp, guard stores
    const int ebase = blockIdx.x * EPB + sub * EPS + eIdx;
    const float* pX[ME];
#pragma unroll
    for (int m = 0; m < ME; m++) {
        const int ge = ebase + m * ET;
        pX[m] = x + (size_t)((ge < B) ? ge : 0) * T_LEN;
    }

    float* sHsub = sH + sub * FH_SUB;

    float c[ME][NU];
#pragma unroll
    for (int m = 0; m < ME; m++)
#pragma unroll
        for (int s = 0; s < NU; s++) c[m][s] = 0.0f;

    const float L2E = 1.4426950408889634f;

    for (int t = 0; t < T_LEN; t++) {
        const float* hin  = sHsub + (t & 1) * (EPS * HSTR) + eIdx * HSTR;
        float*       hout = sHsub + ((t + 1) & 1) * (EPS * HSTR) + eIdx * HSTR;

        float xv[ME];
#pragma unroll
        for (int m = 0; m < ME; m++) xv[m] = __ldg(pX[m] + t);

        // ---- 8x4 register tile over k, packed f32x2 (13 float4 chunks) ----
        unsigned long long acc[NROW][ME];
#pragma unroll
        for (int r = 0; r < NROW; r++)
#pragma unroll
            for (int m = 0; m < ME; m++) acc[r][m] = 0ull;

#pragma unroll
        for (int k4 = 0; k4 < KD / 4; k4++) {
            ulonglong2 wv[NROW];
#pragma unroll
            for (int r = 0; r < NROW; r++) {
                const int gate = r >> 1, s = r & 1;
                wv[r] = *reinterpret_cast<const ulonglong2*>(
                    sW + (gate * RPAD + u0 + s) * KD + 4 * k4);
            }
#pragma unroll
            for (int m = 0; m < ME; m++) {
                const ulonglong2 hv = *reinterpret_cast<const ulonglong2*>(
                    hin + m * (ET * HSTR) + 4 * k4);
#pragma unroll
                for (int r = 0; r < NROW; r++) {
                    ffma2(acc[r][m], wv[r].x, hv.x);
                    ffma2(acc[r][m], wv[r].y, hv.y);
                }
            }
        }

        // ---- fused fold + activation + cell update (no act[] array) ----
#pragma unroll
        for (int m = 0; m < ME; m++) {
            float2 hnew;
#pragma unroll
            for (int s = 0; s < NU; s++) {
                float g4[4];
#pragma unroll
                for (int gate = 0; gate < 4; gate++) {
                    U64F2 u; u.u = acc[gate * NU + s][m];
                    const int bi = gate * RPAD + u0 + s;
                    const float pre = (u.f.x + u.f.y)
                                    + fmaf(xv[m], sWih[bi], sBias[bi]);
                    const float k1 = (gate == 2) ? (-2.0f * L2E) : (-L2E);
                    const float am = (gate == 2) ? 2.0f : 1.0f;
                    const float aa = (gate == 2) ? -1.0f : 0.0f;
                    const float e2 = fast_ex2(k1 * pre);
                    const float rr = fast_rcp(1.0f + e2);
                    g4[gate] = fmaf(am, rr, aa);
                }
                const float cj = fmaf(g4[1], c[m][s], g4[0] * g4[2]);
                c[m][s] = cj;
                const float e2 = fast_ex2(-2.0f * L2E * cj);
                const float rr = fast_rcp(1.0f + e2);
                const float hj = g4[3] * fmaf(2.0f, rr, -1.0f);
                (s == 0 ? hnew.x : hnew.y) = hj;
            }
            if (live)
                *reinterpret_cast<float2*>(hout + m * (ET * HSTR) + u0) = hnew;
        }

        // subgroup-scoped barrier: 7 warps, one per step
        asm volatile("bar.sync %0, %1;" :: "r"(sub + 1), "r"(SUBT) : "memory");
    }

    __syncthreads();   // head threads read the other subgroup's sH

    // ---- head: h_T in buffer 0 (T even); one thread per element ----
    if (tid < EPB) {
        const int ge = blockIdx.x * EPB + tid;
        if (ge < B) {
            const int hsub = tid >> 5, el = tid & 31;    // 32 el per subgroup
            const float* hrow = sH + hsub * FH_SUB + el * HSTR;  // buf 0
            float y = sBl[0];
#pragma unroll
            for (int j = 0; j < HID; j++) y = fmaf(hrow[j], sWl[j], y);
            out[ge] = y;
        }
    }
}

extern "C" void kernel_launch(void* const* d_in, const int* in_sizes, int n_in,
                              void* d_out, int out_size) {
    const float* x     = (const float*)d_in[0];
    const float* W_ih  = (const float*)d_in[1];
    const float* W_hh  = (const float*)d_in[2];
    const float* b_ih  = (const float*)d_in[3];
    const float* b_hh  = (const float*)d_in[4];
    const float* W_lin = (const float*)d_in[5];
    const float* b_lin = (const float*)d_in[6];
    float* out = (float*)d_out;

    const int B = out_size;                    // [B,1]
    const int blocks = (B + EPB - 1) / EPB;    // 128 for B=8192

    static int smem_set = 0;
    if (!smem_set) {
        cudaFuncSetAttribute(lstm_r16_kernel,
                             cudaFuncAttributeMaxDynamicSharedMemorySize,
                             SM_TOT);
        smem_set = 1;
    }
    lstm_r16_kernel<<<blocks, NTHR, SM_TOT>>>(x, W_ih, W_hh, b_ih, b_hh,
                                              W_lin, b_lin, out, B);
}